// round 3
// baseline (speedup 1.0000x reference)
#include <cuda_runtime.h>

#define Nn   4096
#define Bb   4
#define Kk   8
#define TPB  128
#define NBLK ((Nn / TPB) * Bb)   // 128 blocks
#define EPSF 1e-12f

__device__ float g_partials[3 * NBLK];

// Scan all Nn candidates in smem, keep 9 smallest squared distances (ascending,
// ties -> lower index first, matching lax.top_k stability with monotonic j).
__device__ __forceinline__ void scan9(const float4* __restrict__ s,
                                      float px, float py, float pz, float sq,
                                      float bd[9], int bi[9]) {
#pragma unroll
    for (int t = 0; t < 9; t++) { bd[t] = 3.4e38f; bi[t] = 0; }
    float m2x = -2.0f * px, m2y = -2.0f * py, m2z = -2.0f * pz;
#pragma unroll 4
    for (int j = 0; j < Nn; j++) {
        float4 q  = s[j];
        float base = sq + q.w;
        float d2 = fmaf(m2x, q.x, fmaf(m2y, q.y, fmaf(m2z, q.z, base)));
        if (d2 < bd[8]) {
            float v = d2; int vi = j;
#pragma unroll
            for (int t = 0; t < 9; t++) {
                bool c = v < bd[t];
                float od = bd[t]; int oi = bi[t];
                bd[t] = c ? v  : od;
                bi[t] = c ? vi : oi;
                v  = c ? od : v;
                vi = c ? oi : vi;
            }
        }
    }
}

__global__ void __launch_bounds__(TPB)
knn_loss_kernel(const float* __restrict__ pred, const float* __restrict__ target) {
    extern __shared__ float4 smem[];
    float4* sp = smem;        // pred points of this batch  (x,y,z,|x|^2)
    float4* st = smem + Nn;   // target points of this batch

    const int tid = threadIdx.x;
    const int b   = blockIdx.y;

    const float* pb = pred   + (size_t)b * Nn * 3;
    const float* tb = target + (size_t)b * Nn * 3;
    for (int p = tid; p < Nn; p += TPB) {
        float x = pb[3*p+0], y = pb[3*p+1], z = pb[3*p+2];
        sp[p] = make_float4(x, y, z, fmaf(x, x, fmaf(y, y, z*z)));
        float a = tb[3*p+0], c = tb[3*p+1], d = tb[3*p+2];
        st[p] = make_float4(a, c, d, fmaf(a, a, fmaf(c, c, d*d)));
    }
    __syncthreads();

    const int i = blockIdx.x * TPB + tid;
    const float4 Pi = sp[i];
    const float4 Ti = st[i];

    float bd[9]; int bi[9];

    // ---- pred kNN ----
    scan9(sp, Pi.x, Pi.y, Pi.z, Pi.w, bd, bi);

    float pnx[Kk], pny[Kk], pnz[Kk];              // normalized pred vecs
    float pxx = 0.f, pyy = 0.f, pzz = 0.f, pxy = 0.f, pxz = 0.f, pyz = 0.f;
    float pdens = 0.f;
#pragma unroll
    for (int k = 0; k < Kk; k++) {
        pdens += sqrtf(fmaxf(bd[k+1], EPSF));     // neighbor distance (clamped)
        float4 q = sp[bi[k+1]];
        float vx = q.x - Pi.x, vy = q.y - Pi.y, vz = q.z - Pi.z;
        pxx = fmaf(vx, vx, pxx); pyy = fmaf(vy, vy, pyy); pzz = fmaf(vz, vz, pzz);
        pxy = fmaf(vx, vy, pxy); pxz = fmaf(vx, vz, pxz); pyz = fmaf(vy, vz, pyz);
        float nrm = sqrtf(fmaf(vx, vx, fmaf(vy, vy, vz * vz)));
        float inv = 1.0f / fmaxf(nrm, EPSF);
        pnx[k] = vx * inv; pny[k] = vy * inv; pnz[k] = vz * inv;
    }
    pdens *= 0.125f;
    pxx *= 0.125f; pyy *= 0.125f; pzz *= 0.125f;
    pxy *= 0.125f; pxz *= 0.125f; pyz *= 0.125f;

    // ---- target kNN ----
    scan9(st, Ti.x, Ti.y, Ti.z, Ti.w, bd, bi);

    float txx = 0.f, tyy = 0.f, tzz = 0.f, txy = 0.f, txz = 0.f, tyz = 0.f;
    float tdens = 0.f, dsum = 0.f;
#pragma unroll
    for (int k = 0; k < Kk; k++) {
        tdens += sqrtf(fmaxf(bd[k+1], EPSF));
        float4 q = st[bi[k+1]];
        float vx = q.x - Ti.x, vy = q.y - Ti.y, vz = q.z - Ti.z;
        txx = fmaf(vx, vx, txx); tyy = fmaf(vy, vy, tyy); tzz = fmaf(vz, vz, tzz);
        txy = fmaf(vx, vy, txy); txz = fmaf(vx, vz, txz); tyz = fmaf(vy, vz, tyz);
        float nrm = sqrtf(fmaf(vx, vx, fmaf(vy, vy, vz * vz)));
        float inv = 1.0f / fmaxf(nrm, EPSF);
        dsum = fmaf(pnx[k], vx * inv, dsum);
        dsum = fmaf(pny[k], vy * inv, dsum);
        dsum = fmaf(pnz[k], vz * inv, dsum);
    }
    tdens *= 0.125f;
    txx *= 0.125f; tyy *= 0.125f; tzz *= 0.125f;
    txy *= 0.125f; txz *= 0.125f; tyz *= 0.125f;

    float dd = pdens - tdens;
    float c_den = dd * dd;
    float exx = pxx - txx, eyy = pyy - tyy, ezz = pzz - tzz;
    float exy = pxy - txy, exz = pxz - txz, eyz = pyz - tyz;
    float fro = exx*exx + eyy*eyy + ezz*ezz + 2.0f*(exy*exy + exz*exz + eyz*eyz);
    float c_cur = sqrtf(fro);

    // ---- block reduction (reuse smem after all gathers complete) ----
    __syncthreads();
    float* red = (float*)smem;
    red[tid]          = c_den;
    red[TPB + tid]    = dsum;
    red[2*TPB + tid]  = c_cur;
    __syncthreads();
#pragma unroll
    for (int s = TPB / 2; s > 0; s >>= 1) {
        if (tid < s) {
            red[tid]         += red[tid + s];
            red[TPB + tid]   += red[TPB + tid + s];
            red[2*TPB + tid] += red[2*TPB + tid + s];
        }
        __syncthreads();
    }
    if (tid == 0) {
        int blk = blockIdx.y * gridDim.x + blockIdx.x;
        g_partials[blk]           = red[0];
        g_partials[NBLK + blk]    = red[TPB];
        g_partials[2*NBLK + blk]  = red[2*TPB];
    }
}

__global__ void __launch_bounds__(NBLK) finalize_kernel(float* __restrict__ out) {
    __shared__ float r[3 * NBLK];
    int tid = threadIdx.x;
    r[tid]          = g_partials[tid];
    r[NBLK + tid]   = g_partials[NBLK + tid];
    r[2*NBLK + tid] = g_partials[2*NBLK + tid];
    __syncthreads();
#pragma unroll
    for (int s = NBLK / 2; s > 0; s >>= 1) {
        if (tid < s) {
            r[tid]          += r[tid + s];
            r[NBLK + tid]   += r[NBLK + tid + s];
            r[2*NBLK + tid] += r[2*NBLK + tid + s];
        }
        __syncthreads();
    }
    if (tid == 0) {
        const float invBN = 1.0f / (float)(Bb * Nn);
        float density_loss   = r[0] * invBN;
        float direction_loss = 1.0f - r[NBLK] * (invBN / (float)Kk);
        float curvature_loss = r[2*NBLK] * invBN;
        out[0] = density_loss + 0.5f * direction_loss + 0.5f * curvature_loss;
    }
}

extern "C" void kernel_launch(void* const* d_in, const int* in_sizes, int n_in,
                              void* d_out, int out_size) {
    (void)in_sizes; (void)n_in; (void)out_size;
    const float* pred   = (const float*)d_in[0];
    const float* target = (const float*)d_in[1];

    size_t smem_bytes = 2 * Nn * sizeof(float4);   // 128 KB
    cudaFuncSetAttribute(knn_loss_kernel,
                         cudaFuncAttributeMaxDynamicSharedMemorySize,
                         (int)smem_bytes);

    dim3 grid(Nn / TPB, Bb);
    knn_loss_kernel<<<grid, TPB, smem_bytes>>>(pred, target);
    finalize_kernel<<<1, NBLK>>>((float*)d_out);
}

// round 4
// speedup vs baseline: 1.0008x; 1.0008x over previous
#include <cuda_runtime.h>

#define Nn   4096
#define Bb   4
#define Kk   8
#define TPB  128
#define NBLK ((Nn / TPB) * Bb)   // 128 blocks
#define EPSF 1e-12f

__device__ float g_partials[3 * NBLK];

// Scan all Nn candidates in smem, keep 9 smallest squared distances (ascending,
// ties -> lower index first, matching lax.top_k stability with monotonic j).
__device__ __forceinline__ void scan9(const float4* __restrict__ s,
                                      float px, float py, float pz, float sq,
                                      float bd[9], int bi[9]) {
#pragma unroll
    for (int t = 0; t < 9; t++) { bd[t] = 3.4e38f; bi[t] = 0; }
    float m2x = -2.0f * px, m2y = -2.0f * py, m2z = -2.0f * pz;
#pragma unroll 4
    for (int j = 0; j < Nn; j++) {
        float4 q  = s[j];
        float base = sq + q.w;
        float d2 = fmaf(m2x, q.x, fmaf(m2y, q.y, fmaf(m2z, q.z, base)));
        if (d2 < bd[8]) {
            float v = d2; int vi = j;
#pragma unroll
            for (int t = 0; t < 9; t++) {
                bool c = v < bd[t];
                float od = bd[t]; int oi = bi[t];
                bd[t] = c ? v  : od;
                bi[t] = c ? vi : oi;
                v  = c ? od : v;
                vi = c ? oi : vi;
            }
        }
    }
}

__global__ void __launch_bounds__(TPB)
knn_loss_kernel(const float* __restrict__ pred, const float* __restrict__ target) {
    extern __shared__ float4 smem[];
    float4* sp = smem;        // pred points of this batch  (x,y,z,|x|^2)
    float4* st = smem + Nn;   // target points of this batch

    const int tid = threadIdx.x;
    const int b   = blockIdx.y;

    const float* pb = pred   + (size_t)b * Nn * 3;
    const float* tb = target + (size_t)b * Nn * 3;
    for (int p = tid; p < Nn; p += TPB) {
        float x = pb[3*p+0], y = pb[3*p+1], z = pb[3*p+2];
        sp[p] = make_float4(x, y, z, fmaf(x, x, fmaf(y, y, z*z)));
        float a = tb[3*p+0], c = tb[3*p+1], d = tb[3*p+2];
        st[p] = make_float4(a, c, d, fmaf(a, a, fmaf(c, c, d*d)));
    }
    __syncthreads();

    const int i = blockIdx.x * TPB + tid;
    const float4 Pi = sp[i];
    const float4 Ti = st[i];

    float bd[9]; int bi[9];

    // ---- pred kNN ----
    scan9(sp, Pi.x, Pi.y, Pi.z, Pi.w, bd, bi);

    float pnx[Kk], pny[Kk], pnz[Kk];              // normalized pred vecs
    float pxx = 0.f, pyy = 0.f, pzz = 0.f, pxy = 0.f, pxz = 0.f, pyz = 0.f;
    float pdens = 0.f;
#pragma unroll
    for (int k = 0; k < Kk; k++) {
        pdens += sqrtf(fmaxf(bd[k+1], EPSF));     // neighbor distance (clamped)
        float4 q = sp[bi[k+1]];
        float vx = q.x - Pi.x, vy = q.y - Pi.y, vz = q.z - Pi.z;
        pxx = fmaf(vx, vx, pxx); pyy = fmaf(vy, vy, pyy); pzz = fmaf(vz, vz, pzz);
        pxy = fmaf(vx, vy, pxy); pxz = fmaf(vx, vz, pxz); pyz = fmaf(vy, vz, pyz);
        float nrm = sqrtf(fmaf(vx, vx, fmaf(vy, vy, vz * vz)));
        float inv = 1.0f / fmaxf(nrm, EPSF);
        pnx[k] = vx * inv; pny[k] = vy * inv; pnz[k] = vz * inv;
    }
    pdens *= 0.125f;
    pxx *= 0.125f; pyy *= 0.125f; pzz *= 0.125f;
    pxy *= 0.125f; pxz *= 0.125f; pyz *= 0.125f;

    // ---- target kNN ----
    scan9(st, Ti.x, Ti.y, Ti.z, Ti.w, bd, bi);

    float txx = 0.f, tyy = 0.f, tzz = 0.f, txy = 0.f, txz = 0.f, tyz = 0.f;
    float tdens = 0.f, dsum = 0.f;
#pragma unroll
    for (int k = 0; k < Kk; k++) {
        tdens += sqrtf(fmaxf(bd[k+1], EPSF));
        float4 q = st[bi[k+1]];
        float vx = q.x - Ti.x, vy = q.y - Ti.y, vz = q.z - Ti.z;
        txx = fmaf(vx, vx, txx); tyy = fmaf(vy, vy, tyy); tzz = fmaf(vz, vz, tzz);
        txy = fmaf(vx, vy, txy); txz = fmaf(vx, vz, txz); tyz = fmaf(vy, vz, tyz);
        float nrm = sqrtf(fmaf(vx, vx, fmaf(vy, vy, vz * vz)));
        float inv = 1.0f / fmaxf(nrm, EPSF);
        dsum = fmaf(pnx[k], vx * inv, dsum);
        dsum = fmaf(pny[k], vy * inv, dsum);
        dsum = fmaf(pnz[k], vz * inv, dsum);
    }
    tdens *= 0.125f;
    txx *= 0.125f; tyy *= 0.125f; tzz *= 0.125f;
    txy *= 0.125f; txz *= 0.125f; tyz *= 0.125f;

    float dd = pdens - tdens;
    float c_den = dd * dd;
    float exx = pxx - txx, eyy = pyy - tyy, ezz = pzz - tzz;
    float exy = pxy - txy, exz = pxz - txz, eyz = pyz - tyz;
    float fro = exx*exx + eyy*eyy + ezz*ezz + 2.0f*(exy*exy + exz*exz + eyz*eyz);
    float c_cur = sqrtf(fro);

    // ---- block reduction (reuse smem after all gathers complete) ----
    __syncthreads();
    float* red = (float*)smem;
    red[tid]          = c_den;
    red[TPB + tid]    = dsum;
    red[2*TPB + tid]  = c_cur;
    __syncthreads();
#pragma unroll
    for (int s = TPB / 2; s > 0; s >>= 1) {
        if (tid < s) {
            red[tid]         += red[tid + s];
            red[TPB + tid]   += red[TPB + tid + s];
            red[2*TPB + tid] += red[2*TPB + tid + s];
        }
        __syncthreads();
    }
    if (tid == 0) {
        int blk = blockIdx.y * gridDim.x + blockIdx.x;
        g_partials[blk]           = red[0];
        g_partials[NBLK + blk]    = red[TPB];
        g_partials[2*NBLK + blk]  = red[2*TPB];
    }
}

__global__ void __launch_bounds__(NBLK) finalize_kernel(float* __restrict__ out) {
    __shared__ float r[3 * NBLK];
    int tid = threadIdx.x;
    r[tid]          = g_partials[tid];
    r[NBLK + tid]   = g_partials[NBLK + tid];
    r[2*NBLK + tid] = g_partials[2*NBLK + tid];
    __syncthreads();
#pragma unroll
    for (int s = NBLK / 2; s > 0; s >>= 1) {
        if (tid < s) {
            r[tid]          += r[tid + s];
            r[NBLK + tid]   += r[NBLK + tid + s];
            r[2*NBLK + tid] += r[2*NBLK + tid + s];
        }
        __syncthreads();
    }
    if (tid == 0) {
        const float invBN = 1.0f / (float)(Bb * Nn);
        float density_loss   = r[0] * invBN;
        float direction_loss = 1.0f - r[NBLK] * (invBN / (float)Kk);
        float curvature_loss = r[2*NBLK] * invBN;
        out[0] = density_loss + 0.5f * direction_loss + 0.5f * curvature_loss;
    }
}

extern "C" void kernel_launch(void* const* d_in, const int* in_sizes, int n_in,
                              void* d_out, int out_size) {
    (void)in_sizes; (void)n_in; (void)out_size;
    const float* pred   = (const float*)d_in[0];
    const float* target = (const float*)d_in[1];

    size_t smem_bytes = 2 * Nn * sizeof(float4);   // 128 KB
    cudaFuncSetAttribute(knn_loss_kernel,
                         cudaFuncAttributeMaxDynamicSharedMemorySize,
                         (int)smem_bytes);

    dim3 grid(Nn / TPB, Bb);
    knn_loss_kernel<<<grid, TPB, smem_bytes>>>(pred, target);
    finalize_kernel<<<1, NBLK>>>((float*)d_out);
}

// round 5
// speedup vs baseline: 1.5401x; 1.5388x over previous
#include <cuda_runtime.h>

#define Nn   4096
#define Bb   4
#define Kk   8
#define BN   (Bb * Nn)          // 16384 points per cloud
#define TPB  256
#define CB   64                 // combine blocks (BN / TPB)
#define EPSF 1e-12f

// ---- device scratch (SoA, coalesced) ----
__device__ float g_dens[2 * BN];            // [cloud][b*Nn+p]
__device__ float g_cov [2 * 6 * BN];        // [cloud][s][point]
__device__ float g_nv  [2 * Kk * 3 * BN];   // [cloud][k][comp][point]
__device__ float g_part[3 * CB];

// Scan all Nn candidates in smem, keep 9 smallest squared distances
// (ascending; ties -> lower index first).
__device__ __forceinline__ void scan9(const float4* __restrict__ s,
                                      float px, float py, float pz, float sq,
                                      float bd[9], int bi[9]) {
#pragma unroll
    for (int t = 0; t < 9; t++) { bd[t] = 3.4e38f; bi[t] = 0; }
    float m2x = -2.0f * px, m2y = -2.0f * py, m2z = -2.0f * pz;
#pragma unroll 4
    for (int j = 0; j < Nn; j++) {
        float4 q = s[j];
        float base = sq + q.w;
        float d2 = fmaf(m2x, q.x, fmaf(m2y, q.y, fmaf(m2z, q.z, base)));
        if (d2 < bd[8]) {
            float v = d2; int vi = j;
#pragma unroll
            for (int t = 0; t < 9; t++) {
                bool c = v < bd[t];
                float od = bd[t]; int oi = bi[t];
                bd[t] = c ? v  : od;
                bi[t] = c ? vi : oi;
                v  = c ? od : v;
                vi = c ? oi : vi;
            }
        }
    }
}

// One block = 256 points of one (batch, cloud). smem = 64 KB (one cloud).
__global__ void __launch_bounds__(TPB)
knn_scan_kernel(const float* __restrict__ pred, const float* __restrict__ target) {
    extern __shared__ float4 smem[];
    const int tid = threadIdx.x;
    const int b   = blockIdx.y;
    const int c   = blockIdx.z;          // 0 = pred, 1 = target

    const float* src = (c == 0 ? pred : target) + (size_t)b * Nn * 3;
    for (int p = tid; p < Nn; p += TPB) {
        float x = src[3*p+0], y = src[3*p+1], z = src[3*p+2];
        smem[p] = make_float4(x, y, z, fmaf(x, x, fmaf(y, y, z*z)));
    }
    __syncthreads();

    const int i  = blockIdx.x * TPB + tid;
    const float4 Pi = smem[i];

    float bd[9]; int bi[9];
    scan9(smem, Pi.x, Pi.y, Pi.z, Pi.w, bd, bi);

    const int base = b * Nn + i;
    float dens = 0.f;
    float cxx = 0.f, cyy = 0.f, czz = 0.f, cxy = 0.f, cxz = 0.f, cyz = 0.f;
#pragma unroll
    for (int k = 0; k < Kk; k++) {
        dens += sqrtf(fmaxf(bd[k+1], EPSF));
        float4 q = smem[bi[k+1]];
        float vx = q.x - Pi.x, vy = q.y - Pi.y, vz = q.z - Pi.z;
        cxx = fmaf(vx, vx, cxx); cyy = fmaf(vy, vy, cyy); czz = fmaf(vz, vz, czz);
        cxy = fmaf(vx, vy, cxy); cxz = fmaf(vx, vz, cxz); cyz = fmaf(vy, vz, cyz);
        float nrm = sqrtf(fmaf(vx, vx, fmaf(vy, vy, vz * vz)));
        float inv = 1.0f / fmaxf(nrm, EPSF);
        g_nv[((c*Kk + k)*3 + 0)*BN + base] = vx * inv;
        g_nv[((c*Kk + k)*3 + 1)*BN + base] = vy * inv;
        g_nv[((c*Kk + k)*3 + 2)*BN + base] = vz * inv;
    }
    g_dens[c*BN + base]      = dens * 0.125f;
    g_cov[(c*6 + 0)*BN + base] = cxx * 0.125f;
    g_cov[(c*6 + 1)*BN + base] = cyy * 0.125f;
    g_cov[(c*6 + 2)*BN + base] = czz * 0.125f;
    g_cov[(c*6 + 3)*BN + base] = cxy * 0.125f;
    g_cov[(c*6 + 4)*BN + base] = cxz * 0.125f;
    g_cov[(c*6 + 5)*BN + base] = cyz * 0.125f;
}

// Pair pred/target stats per point, partial-reduce per block.
__global__ void __launch_bounds__(TPB)
combine_kernel() {
    const int tid = threadIdx.x;
    const int idx = blockIdx.x * TPB + tid;

    float pd = g_dens[idx], td = g_dens[BN + idx];
    float dd = pd - td;
    float c_den = dd * dd;

    float fro = 0.f;
#pragma unroll
    for (int s = 0; s < 6; s++) {
        float e = g_cov[s*BN + idx] - g_cov[(6 + s)*BN + idx];
        float w = (s < 3) ? 1.0f : 2.0f;
        fro = fmaf(w * e, e, fro);
    }
    float c_cur = sqrtf(fro);

    float dsum = 0.f;
#pragma unroll
    for (int e = 0; e < Kk * 3; e++) {
        dsum = fmaf(g_nv[e*BN + idx], g_nv[(Kk*3 + e)*BN + idx], dsum);
    }

    __shared__ float r[3 * TPB];
    r[tid]         = c_den;
    r[TPB + tid]   = dsum;
    r[2*TPB + tid] = c_cur;
    __syncthreads();
#pragma unroll
    for (int s = TPB / 2; s > 0; s >>= 1) {
        if (tid < s) {
            r[tid]         += r[tid + s];
            r[TPB + tid]   += r[TPB + tid + s];
            r[2*TPB + tid] += r[2*TPB + tid + s];
        }
        __syncthreads();
    }
    if (tid == 0) {
        g_part[blockIdx.x]        = r[0];
        g_part[CB + blockIdx.x]   = r[TPB];
        g_part[2*CB + blockIdx.x] = r[2*TPB];
    }
}

__global__ void __launch_bounds__(CB) finalize_kernel(float* __restrict__ out) {
    __shared__ float r[3 * CB];
    int tid = threadIdx.x;
    r[tid]        = g_part[tid];
    r[CB + tid]   = g_part[CB + tid];
    r[2*CB + tid] = g_part[2*CB + tid];
    __syncthreads();
#pragma unroll
    for (int s = CB / 2; s > 0; s >>= 1) {
        if (tid < s) {
            r[tid]        += r[tid + s];
            r[CB + tid]   += r[CB + tid + s];
            r[2*CB + tid] += r[2*CB + tid + s];
        }
        __syncthreads();
    }
    if (tid == 0) {
        const float invBN = 1.0f / (float)BN;
        float density_loss   = r[0] * invBN;
        float direction_loss = 1.0f - r[CB] * (invBN / (float)Kk);
        float curvature_loss = r[2*CB] * invBN;
        out[0] = density_loss + 0.5f * direction_loss + 0.5f * curvature_loss;
    }
}

extern "C" void kernel_launch(void* const* d_in, const int* in_sizes, int n_in,
                              void* d_out, int out_size) {
    (void)in_sizes; (void)n_in; (void)out_size;
    const float* pred   = (const float*)d_in[0];
    const float* target = (const float*)d_in[1];

    size_t smem_bytes = (size_t)Nn * sizeof(float4);   // 64 KB
    cudaFuncSetAttribute(knn_scan_kernel,
                         cudaFuncAttributeMaxDynamicSharedMemorySize,
                         (int)smem_bytes);

    dim3 grid(Nn / TPB, Bb, 2);                        // 128 blocks
    knn_scan_kernel<<<grid, TPB, smem_bytes>>>(pred, target);
    combine_kernel<<<CB, TPB>>>();
    finalize_kernel<<<1, CB>>>((float*)d_out);
}

// round 6
// speedup vs baseline: 1.6271x; 1.0565x over previous
#include <cuda_runtime.h>

#define Nn   4096
#define Bb   4
#define Kk   8
#define BN   (Bb * Nn)          // 16384 points per cloud
#define TPB  256
#define CB   64                 // combine blocks (BN / TPB)
#define EPSF 1e-12f

// ---- device scratch (SoA, coalesced) ----
__device__ float g_dens[2 * BN];            // [cloud][b*Nn+p]
__device__ float g_cov [2 * 6 * BN];        // [cloud][s][point]
__device__ float g_nv  [2 * Kk * 3 * BN];   // [cloud][k][comp][point]
__device__ float g_part[3 * CB];

// Scan all Nn candidates in smem, keep 9 smallest squared distances
// (ascending; ties -> lower index first).
// Hot loop: 3 FFMA (sq folded into threshold) + FSETP + VOTE.ANY + uniform BRA.
// Insert: warp-uniform, parallel-rank (dep depth ~1 FSETP + 2 SEL).
__device__ __forceinline__ void scan9(const float4* __restrict__ s,
                                      float px, float py, float pz, float sq,
                                      float bd[9], int bi[9]) {
#pragma unroll
    for (int t = 0; t < 9; t++) { bd[t] = 3.4e38f; bi[t] = 0; }
    const float m2x = -2.0f * px, m2y = -2.0f * py, m2z = -2.0f * pz;
    float thr = 3.4e38f;                       // = bd[8] - sq (approx at init)
#pragma unroll 4
    for (int j = 0; j < Nn; j++) {
        float4 q  = s[j];
        // d2' = |q|^2 - 2<p,q>   (actual d2 = d2' + sq)
        float d2p = fmaf(m2x, q.x, fmaf(m2y, q.y, fmaf(m2z, q.z, q.w)));
        bool hit = d2p < thr;
        if (__any_sync(0xffffffffu, hit)) {
            float v = d2p + sq;                // lanes with !hit: v >= bd[8] -> no-op
            bool c[9];
#pragma unroll
            for (int t = 0; t < 9; t++) c[t] = v < bd[t];   // independent compares
#pragma unroll
            for (int t = 8; t >= 1; t--) {                  // in-place shift-down
                bd[t] = c[t] ? (c[t-1] ? bd[t-1] : v) : bd[t];
                bi[t] = c[t] ? (c[t-1] ? bi[t-1] : j) : bi[t];
            }
            bd[0] = c[0] ? v : bd[0];
            bi[0] = c[0] ? j : bi[0];
            thr = bd[8] - sq;
        }
    }
}

// One block = 256 points of one (batch, cloud). smem = 64 KB (one cloud).
__global__ void __launch_bounds__(TPB)
knn_scan_kernel(const float* __restrict__ pred, const float* __restrict__ target) {
    extern __shared__ float4 smem[];
    const int tid = threadIdx.x;
    const int b   = blockIdx.y;
    const int c   = blockIdx.z;          // 0 = pred, 1 = target

    const float* src = (c == 0 ? pred : target) + (size_t)b * Nn * 3;
    for (int p = tid; p < Nn; p += TPB) {
        float x = src[3*p+0], y = src[3*p+1], z = src[3*p+2];
        smem[p] = make_float4(x, y, z, fmaf(x, x, fmaf(y, y, z*z)));
    }
    __syncthreads();

    const int i  = blockIdx.x * TPB + tid;
    const float4 Pi = smem[i];

    float bd[9]; int bi[9];
    scan9(smem, Pi.x, Pi.y, Pi.z, Pi.w, bd, bi);

    const int base = b * Nn + i;
    float dens = 0.f;
    float cxx = 0.f, cyy = 0.f, czz = 0.f, cxy = 0.f, cxz = 0.f, cyz = 0.f;
#pragma unroll
    for (int k = 0; k < Kk; k++) {
        dens += sqrtf(fmaxf(bd[k+1], EPSF));
        float4 q = smem[bi[k+1]];
        float vx = q.x - Pi.x, vy = q.y - Pi.y, vz = q.z - Pi.z;
        cxx = fmaf(vx, vx, cxx); cyy = fmaf(vy, vy, cyy); czz = fmaf(vz, vz, czz);
        cxy = fmaf(vx, vy, cxy); cxz = fmaf(vx, vz, cxz); cyz = fmaf(vy, vz, cyz);
        float nrm = sqrtf(fmaf(vx, vx, fmaf(vy, vy, vz * vz)));
        float inv = 1.0f / fmaxf(nrm, EPSF);
        g_nv[((c*Kk + k)*3 + 0)*BN + base] = vx * inv;
        g_nv[((c*Kk + k)*3 + 1)*BN + base] = vy * inv;
        g_nv[((c*Kk + k)*3 + 2)*BN + base] = vz * inv;
    }
    g_dens[c*BN + base]        = dens * 0.125f;
    g_cov[(c*6 + 0)*BN + base] = cxx * 0.125f;
    g_cov[(c*6 + 1)*BN + base] = cyy * 0.125f;
    g_cov[(c*6 + 2)*BN + base] = czz * 0.125f;
    g_cov[(c*6 + 3)*BN + base] = cxy * 0.125f;
    g_cov[(c*6 + 4)*BN + base] = cxz * 0.125f;
    g_cov[(c*6 + 5)*BN + base] = cyz * 0.125f;
}

// Pair pred/target stats per point, partial-reduce per block.
__global__ void __launch_bounds__(TPB)
combine_kernel() {
    const int tid = threadIdx.x;
    const int idx = blockIdx.x * TPB + tid;

    float pd = g_dens[idx], td = g_dens[BN + idx];
    float dd = pd - td;
    float c_den = dd * dd;

    float fro = 0.f;
#pragma unroll
    for (int s = 0; s < 6; s++) {
        float e = g_cov[s*BN + idx] - g_cov[(6 + s)*BN + idx];
        float w = (s < 3) ? 1.0f : 2.0f;
        fro = fmaf(w * e, e, fro);
    }
    float c_cur = sqrtf(fro);

    float dsum = 0.f;
#pragma unroll
    for (int e = 0; e < Kk * 3; e++) {
        dsum = fmaf(g_nv[e*BN + idx], g_nv[(Kk*3 + e)*BN + idx], dsum);
    }

    __shared__ float r[3 * TPB];
    r[tid]         = c_den;
    r[TPB + tid]   = dsum;
    r[2*TPB + tid] = c_cur;
    __syncthreads();
#pragma unroll
    for (int s = TPB / 2; s > 0; s >>= 1) {
        if (tid < s) {
            r[tid]         += r[tid + s];
            r[TPB + tid]   += r[TPB + tid + s];
            r[2*TPB + tid] += r[2*TPB + tid + s];
        }
        __syncthreads();
    }
    if (tid == 0) {
        g_part[blockIdx.x]        = r[0];
        g_part[CB + blockIdx.x]   = r[TPB];
        g_part[2*CB + blockIdx.x] = r[2*TPB];
    }
}

__global__ void __launch_bounds__(CB) finalize_kernel(float* __restrict__ out) {
    __shared__ float r[3 * CB];
    int tid = threadIdx.x;
    r[tid]        = g_part[tid];
    r[CB + tid]   = g_part[CB + tid];
    r[2*CB + tid] = g_part[2*CB + tid];
    __syncthreads();
#pragma unroll
    for (int s = CB / 2; s > 0; s >>= 1) {
        if (tid < s) {
            r[tid]        += r[tid + s];
            r[CB + tid]   += r[CB + tid + s];
            r[2*CB + tid] += r[2*CB + tid + s];
        }
        __syncthreads();
    }
    if (tid == 0) {
        const float invBN = 1.0f / (float)BN;
        float density_loss   = r[0] * invBN;
        float direction_loss = 1.0f - r[CB] * (invBN / (float)Kk);
        float curvature_loss = r[2*CB] * invBN;
        out[0] = density_loss + 0.5f * direction_loss + 0.5f * curvature_loss;
    }
}

extern "C" void kernel_launch(void* const* d_in, const int* in_sizes, int n_in,
                              void* d_out, int out_size) {
    (void)in_sizes; (void)n_in; (void)out_size;
    const float* pred   = (const float*)d_in[0];
    const float* target = (const float*)d_in[1];

    size_t smem_bytes = (size_t)Nn * sizeof(float4);   // 64 KB
    cudaFuncSetAttribute(knn_scan_kernel,
                         cudaFuncAttributeMaxDynamicSharedMemorySize,
                         (int)smem_bytes);

    dim3 grid(Nn / TPB, Bb, 2);                        // 128 blocks
    knn_scan_kernel<<<grid, TPB, smem_bytes>>>(pred, target);
    combine_kernel<<<CB, TPB>>>();
    finalize_kernel<<<1, CB>>>((float*)d_out);
}

// round 7
// speedup vs baseline: 2.5770x; 1.5837x over previous
#include <cuda_runtime.h>

#define Nn    4096
#define Bb    4
#define Kk    8
#define BN    (Bb * Nn)         // 16384 points per cloud
#define TPB   512               // 256 points/block, 2 threads per point
#define PPB   256               // points per block
#define HALF  (Nn / 2)          // candidates per thread
#define CB    64                // combine blocks (BN / 256)
#define CTPB  256
#define EPSF  1e-12f

// ---- device scratch (SoA, coalesced) ----
__device__ float g_dens[2 * BN];
__device__ float g_cov [2 * 6 * BN];
__device__ float g_nv  [2 * Kk * 3 * BN];
__device__ float g_part[3 * CB];

// Scan HALF candidates starting at j0, keep 9 smallest squared distances
// (ascending; ties -> lower index, guaranteed by monotone j).
__device__ __forceinline__ void scan9(const float4* __restrict__ s, int j0,
                                      float px, float py, float pz, float sq,
                                      float bd[9], int bi[9]) {
#pragma unroll
    for (int t = 0; t < 9; t++) { bd[t] = 3.4e38f; bi[t] = 0; }
    const float m2x = -2.0f * px, m2y = -2.0f * py, m2z = -2.0f * pz;
    float thr = 3.4e38f;                       // = bd[8] - sq
    const int jend = j0 + HALF;
#pragma unroll 4
    for (int j = j0; j < jend; j++) {
        float4 q  = s[j];
        float d2p = fmaf(m2x, q.x, fmaf(m2y, q.y, fmaf(m2z, q.z, q.w)));
        bool hit = d2p < thr;
        if (__any_sync(0xffffffffu, hit)) {
            float v = d2p + sq;
            bool c[9];
#pragma unroll
            for (int t = 0; t < 9; t++) c[t] = v < bd[t];
#pragma unroll
            for (int t = 8; t >= 1; t--) {
                bd[t] = c[t] ? (c[t-1] ? bd[t-1] : v) : bd[t];
                bi[t] = c[t] ? (c[t-1] ? bi[t-1] : j) : bi[t];
            }
            bd[0] = c[0] ? v : bd[0];
            bi[0] = c[0] ? j : bi[0];
            thr = bd[8] - sq;
        }
    }
}

// Block: 256 points of one (batch, cloud), 2 threads/point (candidate halves).
__global__ void __launch_bounds__(TPB)
knn_scan_kernel(const float* __restrict__ pred, const float* __restrict__ target) {
    extern __shared__ char smem_raw[];
    float4* sc   = (float4*)smem_raw;                       // [Nn] cloud
    float*  lstd = (float*)(smem_raw + Nn * sizeof(float4)); // [PPB*9] half-B dists
    int*    lsti = (int*)(lstd + PPB * 9);                   // [PPB*9] half-B idx

    const int tid  = threadIdx.x;
    const int b    = blockIdx.y;
    const int c    = blockIdx.z;             // 0 = pred, 1 = target
    const int pl   = tid & (PPB - 1);        // local point
    const int half = tid >> 8;               // 0 = A, 1 = B

    const float* src = (c == 0 ? pred : target) + (size_t)b * Nn * 3;
    for (int p = tid; p < Nn; p += TPB) {
        float x = src[3*p+0], y = src[3*p+1], z = src[3*p+2];
        sc[p] = make_float4(x, y, z, fmaf(x, x, fmaf(y, y, z*z)));
    }
    __syncthreads();

    const int i  = blockIdx.x * PPB + pl;
    const float4 Pi = sc[i];

    float bd[9]; int bi[9];
    scan9(sc, half * HALF, Pi.x, Pi.y, Pi.z, Pi.w, bd, bi);

    // half-B publishes its list
    if (half == 1) {
#pragma unroll
        for (int t = 0; t < 9; t++) {
            lstd[pl * 9 + t] = bd[t];
            lsti[pl * 9 + t] = bi[t];
        }
    }
    __syncthreads();
    if (half == 1) return;

    // ---- merge A (regs) with B (smem) : 9 smallest, ties -> A (lower idx) ----
    float od[9]; int oi[9];
    {
        float ed[9]; int ei[9];
#pragma unroll
        for (int t = 0; t < 9; t++) { ed[t] = lstd[pl * 9 + t]; ei[t] = lsti[pl * 9 + t]; }
#pragma unroll
        for (int r = 0; r < 9; r++) {
            bool ta = bd[0] <= ed[0];          // A indices always < B indices
            od[r] = ta ? bd[0] : ed[0];
            oi[r] = ta ? bi[0] : ei[0];
#pragma unroll
            for (int t = 0; t < 8; t++) {
                bd[t] = ta ? bd[t+1] : bd[t];
                bi[t] = ta ? bi[t+1] : bi[t];
                ed[t] = ta ? ed[t]   : ed[t+1];
                ei[t] = ta ? ei[t]   : ei[t+1];
            }
            bd[8] = ta ? 3.4e38f : bd[8];
            ed[8] = ta ? ed[8]   : 3.4e38f;
        }
    }

    // ---- epilogue: density, covariance, normalized neighbor vectors ----
    const int base = b * Nn + i;
    float dens = 0.f;
    float cxx = 0.f, cyy = 0.f, czz = 0.f, cxy = 0.f, cxz = 0.f, cyz = 0.f;
#pragma unroll
    for (int k = 0; k < Kk; k++) {
        dens += sqrtf(fmaxf(od[k+1], EPSF));
        float4 q = sc[oi[k+1]];
        float vx = q.x - Pi.x, vy = q.y - Pi.y, vz = q.z - Pi.z;
        cxx = fmaf(vx, vx, cxx); cyy = fmaf(vy, vy, cyy); czz = fmaf(vz, vz, czz);
        cxy = fmaf(vx, vy, cxy); cxz = fmaf(vx, vz, cxz); cyz = fmaf(vy, vz, cyz);
        float nrm = sqrtf(fmaf(vx, vx, fmaf(vy, vy, vz * vz)));
        float inv = 1.0f / fmaxf(nrm, EPSF);
        g_nv[((c*Kk + k)*3 + 0)*BN + base] = vx * inv;
        g_nv[((c*Kk + k)*3 + 1)*BN + base] = vy * inv;
        g_nv[((c*Kk + k)*3 + 2)*BN + base] = vz * inv;
    }
    g_dens[c*BN + base]        = dens * 0.125f;
    g_cov[(c*6 + 0)*BN + base] = cxx * 0.125f;
    g_cov[(c*6 + 1)*BN + base] = cyy * 0.125f;
    g_cov[(c*6 + 2)*BN + base] = czz * 0.125f;
    g_cov[(c*6 + 3)*BN + base] = cxy * 0.125f;
    g_cov[(c*6 + 4)*BN + base] = cxz * 0.125f;
    g_cov[(c*6 + 5)*BN + base] = cyz * 0.125f;
}

// Pair pred/target stats per point, partial-reduce per block.
__global__ void __launch_bounds__(CTPB)
combine_kernel() {
    const int tid = threadIdx.x;
    const int idx = blockIdx.x * CTPB + tid;

    float dd = g_dens[idx] - g_dens[BN + idx];
    float c_den = dd * dd;

    float fro = 0.f;
#pragma unroll
    for (int s = 0; s < 6; s++) {
        float e = g_cov[s*BN + idx] - g_cov[(6 + s)*BN + idx];
        float w = (s < 3) ? 1.0f : 2.0f;
        fro = fmaf(w * e, e, fro);
    }
    float c_cur = sqrtf(fro);

    float dsum = 0.f;
#pragma unroll
    for (int e = 0; e < Kk * 3; e++)
        dsum = fmaf(g_nv[e*BN + idx], g_nv[(Kk*3 + e)*BN + idx], dsum);

    __shared__ float r[3 * CTPB];
    r[tid]          = c_den;
    r[CTPB + tid]   = dsum;
    r[2*CTPB + tid] = c_cur;
    __syncthreads();
#pragma unroll
    for (int s = CTPB / 2; s > 0; s >>= 1) {
        if (tid < s) {
            r[tid]          += r[tid + s];
            r[CTPB + tid]   += r[CTPB + tid + s];
            r[2*CTPB + tid] += r[2*CTPB + tid + s];
        }
        __syncthreads();
    }
    if (tid == 0) {
        g_part[blockIdx.x]        = r[0];
        g_part[CB + blockIdx.x]   = r[CTPB];
        g_part[2*CB + blockIdx.x] = r[2*CTPB];
    }
}

__global__ void __launch_bounds__(CB) finalize_kernel(float* __restrict__ out) {
    __shared__ float r[3 * CB];
    int tid = threadIdx.x;
    r[tid]        = g_part[tid];
    r[CB + tid]   = g_part[CB + tid];
    r[2*CB + tid] = g_part[2*CB + tid];
    __syncthreads();
#pragma unroll
    for (int s = CB / 2; s > 0; s >>= 1) {
        if (tid < s) {
            r[tid]        += r[tid + s];
            r[CB + tid]   += r[CB + tid + s];
            r[2*CB + tid] += r[2*CB + tid + s];
        }
        __syncthreads();
    }
    if (tid == 0) {
        const float invBN = 1.0f / (float)BN;
        float density_loss   = r[0] * invBN;
        float direction_loss = 1.0f - r[CB] * (invBN / (float)Kk);
        float curvature_loss = r[2*CB] * invBN;
        out[0] = density_loss + 0.5f * direction_loss + 0.5f * curvature_loss;
    }
}

extern "C" void kernel_launch(void* const* d_in, const int* in_sizes, int n_in,
                              void* d_out, int out_size) {
    (void)in_sizes; (void)n_in; (void)out_size;
    const float* pred   = (const float*)d_in[0];
    const float* target = (const float*)d_in[1];

    size_t smem_bytes = (size_t)Nn * sizeof(float4)
                      + (size_t)PPB * 9 * (sizeof(float) + sizeof(int)); // ~82 KB
    cudaFuncSetAttribute(knn_scan_kernel,
                         cudaFuncAttributeMaxDynamicSharedMemorySize,
                         (int)smem_bytes);

    dim3 grid(Nn / PPB, Bb, 2);                 // 128 blocks, 512 threads each
    knn_scan_kernel<<<grid, TPB, smem_bytes>>>(pred, target);
    combine_kernel<<<CB, CTPB>>>();
    finalize_kernel<<<1, CB>>>((float*)d_out);
}